// round 1
// baseline (speedup 1.0000x reference)
#include <cuda_runtime.h>

// out[b,i,:] = softmax_j(key[j]·wk + c) @ value  — independent of x entirely,
// because scores = sx[b,i] + sk[j] + b and softmax over j drops row constants.

__device__ float g_o[3];

__global__ void reduce_kernel(const float* __restrict__ key,
                              const float* __restrict__ value,
                              const float* __restrict__ W) {
    __shared__ float sk[2048];
    __shared__ float red[256];
    __shared__ float red0[256], red1[256], red2[256], red3[256];

    const int tid = threadIdx.x;
    const float wk0 = W[3], wk1 = W[4], wk2 = W[5];

    // Pass 1: sk[j] = key[j] . wk, track local max
    float lmax = -1e30f;
    #pragma unroll
    for (int j = tid; j < 2048; j += 256) {
        float k0 = key[3 * j + 0];
        float k1 = key[3 * j + 1];
        float k2 = key[3 * j + 2];
        float s = fmaf(k0, wk0, fmaf(k1, wk1, k2 * wk2));
        sk[j] = s;
        lmax = fmaxf(lmax, s);
    }
    red[tid] = lmax;
    __syncthreads();
    #pragma unroll
    for (int off = 128; off > 0; off >>= 1) {
        if (tid < off) red[tid] = fmaxf(red[tid], red[tid + off]);
        __syncthreads();
    }
    const float m = red[0];

    // Pass 2: accumulate sum(e), sum(e*v0), sum(e*v1), sum(e*v2)
    float se = 0.f, s0 = 0.f, s1 = 0.f, s2 = 0.f;
    #pragma unroll
    for (int j = tid; j < 2048; j += 256) {
        float e = __expf(sk[j] - m);
        se += e;
        s0 = fmaf(e, value[3 * j + 0], s0);
        s1 = fmaf(e, value[3 * j + 1], s1);
        s2 = fmaf(e, value[3 * j + 2], s2);
    }
    red0[tid] = se; red1[tid] = s0; red2[tid] = s1; red3[tid] = s2;
    __syncthreads();
    #pragma unroll
    for (int off = 128; off > 0; off >>= 1) {
        if (tid < off) {
            red0[tid] += red0[tid + off];
            red1[tid] += red1[tid + off];
            red2[tid] += red2[tid + off];
            red3[tid] += red3[tid + off];
        }
        __syncthreads();
    }
    if (tid == 0) {
        float inv = 1.0f / red0[0];
        g_o[0] = red1[0] * inv;
        g_o[1] = red2[0] * inv;
        g_o[2] = red3[0] * inv;
    }
}

// Broadcast o[3] into out (49152 floats). Each thread writes 12 floats
// (3 x float4); pattern has period 12 and 49152 % 12 == 0 -> 4096 threads.
__global__ void broadcast_kernel(float* __restrict__ out) {
    const float o0 = g_o[0], o1 = g_o[1], o2 = g_o[2];
    const int t = blockIdx.x * blockDim.x + threadIdx.x;  // 0..4095
    float4* p = reinterpret_cast<float4*>(out + t * 12);
    p[0] = make_float4(o0, o1, o2, o0);
    p[1] = make_float4(o1, o2, o0, o1);
    p[2] = make_float4(o2, o0, o1, o2);
}

extern "C" void kernel_launch(void* const* d_in, const int* in_sizes, int n_in,
                              void* d_out, int out_size) {
    // inputs: x[0] (unused), key[1], value[2], W[3], b[4] (unused)
    const float* key   = (const float*)d_in[1];
    const float* value = (const float*)d_in[2];
    const float* W     = (const float*)d_in[3];
    float* out = (float*)d_out;

    reduce_kernel<<<1, 256>>>(key, value, W);
    broadcast_kernel<<<4096 / 256, 256>>>(out);  // 4096 threads * 12 floats = 49152
}

// round 2
// speedup vs baseline: 1.4010x; 1.4010x over previous
#include <cuda_runtime.h>

// out[b,i,:] = softmax_j(key[j]·wk + c) @ value — independent of x, because
// scores[b,i,j] = sx[b,i] + sk[j] + b and softmax over j drops row constants.
//
// Single launch: each of 16 CTAs redundantly computes the (tiny) reduction,
// then writes its 3072-float slice of the 49152-float output. No inter-CTA
// dependency -> no second kernel, no grid sync.

__global__ void __launch_bounds__(256, 1)
fused_kernel(const float* __restrict__ key,
             const float* __restrict__ value,
             const float* __restrict__ W,
             float* __restrict__ out) {
    __shared__ float sk[2048];
    __shared__ float wred[32];   // 8 warps x 4 sums
    __shared__ float osh[4];     // o0, o1, o2, max

    const int tid  = threadIdx.x;
    const int lane = tid & 31;
    const int wid  = tid >> 5;

    const float wk0 = W[3], wk1 = W[4], wk2 = W[5];

    // Pass 1: sk[j] = key[j] . wk, track max
    float lmax = -1e30f;
    #pragma unroll
    for (int j = tid; j < 2048; j += 256) {
        float k0 = key[3 * j + 0];
        float k1 = key[3 * j + 1];
        float k2 = key[3 * j + 2];
        float s = fmaf(k0, wk0, fmaf(k1, wk1, k2 * wk2));
        sk[j] = s;
        lmax = fmaxf(lmax, s);
    }
    #pragma unroll
    for (int o = 16; o > 0; o >>= 1)
        lmax = fmaxf(lmax, __shfl_xor_sync(0xffffffffu, lmax, o));
    if (lane == 0) wred[wid] = lmax;
    __syncthreads();
    if (tid < 32) {
        float v = (lane < 8) ? wred[lane] : -1e30f;
        #pragma unroll
        for (int o = 4; o > 0; o >>= 1)
            v = fmaxf(v, __shfl_xor_sync(0xffffffffu, v, o));
        if (lane == 0) osh[3] = v;
    }
    __syncthreads();
    const float m = osh[3];

    // Pass 2: sum(e), sum(e*v0), sum(e*v1), sum(e*v2)
    float se = 0.f, s0 = 0.f, s1 = 0.f, s2 = 0.f;
    #pragma unroll
    for (int j = tid; j < 2048; j += 256) {
        float e = __expf(sk[j] - m);
        se += e;
        s0 = fmaf(e, value[3 * j + 0], s0);
        s1 = fmaf(e, value[3 * j + 1], s1);
        s2 = fmaf(e, value[3 * j + 2], s2);
    }
    #pragma unroll
    for (int o = 16; o > 0; o >>= 1) {
        se += __shfl_xor_sync(0xffffffffu, se, o);
        s0 += __shfl_xor_sync(0xffffffffu, s0, o);
        s1 += __shfl_xor_sync(0xffffffffu, s1, o);
        s2 += __shfl_xor_sync(0xffffffffu, s2, o);
    }
    if (lane == 0) {
        wred[wid]      = se;
        wred[8 + wid]  = s0;
        wred[16 + wid] = s1;
        wred[24 + wid] = s2;
    }
    __syncthreads();
    if (tid < 32) {
        float a = (lane < 8) ? wred[lane]      : 0.f;
        float b = (lane < 8) ? wred[8 + lane]  : 0.f;
        float c = (lane < 8) ? wred[16 + lane] : 0.f;
        float d = (lane < 8) ? wred[24 + lane] : 0.f;
        #pragma unroll
        for (int o = 4; o > 0; o >>= 1) {
            a += __shfl_xor_sync(0xffffffffu, a, o);
            b += __shfl_xor_sync(0xffffffffu, b, o);
            c += __shfl_xor_sync(0xffffffffu, c, o);
            d += __shfl_xor_sync(0xffffffffu, d, o);
        }
        if (lane == 0) {
            float inv = 1.0f / a;
            osh[0] = b * inv;
            osh[1] = c * inv;
            osh[2] = d * inv;
        }
    }
    __syncthreads();

    // Write this CTA's 3072-float slice: 256 threads x 12 floats (3 x float4),
    // period-12 pattern aligns with the 3-float o vector (12 % 3 == 0).
    const float o0 = osh[0], o1 = osh[1], o2 = osh[2];
    float4* p = reinterpret_cast<float4*>(out + blockIdx.x * 3072 + tid * 12);
    p[0] = make_float4(o0, o1, o2, o0);
    p[1] = make_float4(o1, o2, o0, o1);
    p[2] = make_float4(o2, o0, o1, o2);
}

extern "C" void kernel_launch(void* const* d_in, const int* in_sizes, int n_in,
                              void* d_out, int out_size) {
    // inputs: x[0] (unused), key[1], value[2], W[3], b[4] (unused)
    const float* key   = (const float*)d_in[1];
    const float* value = (const float*)d_in[2];
    const float* W     = (const float*)d_in[3];
    float* out = (float*)d_out;

    fused_kernel<<<16, 256>>>(key, value, W, out);  // 16 * 3072 = 49152 floats
}